// round 15
// baseline (speedup 1.0000x reference)
#include <cuda_runtime.h>
#include <math.h>
#include <stdint.h>

#define NBL  4096
#define HIDD 1024
#define OUTC 128
typedef unsigned long long ull;
typedef uint32_t u32;

// ---------------- device scratch (allocation-free rule) ----------------
__device__ __align__(16) float g_Hc[NBL * OUTC];   // hidden @ W1[0:1024] + b1
__device__ __align__(16) float g_Wt[34816];        // W fragments, paired-nb layout
__device__ u32 g_count = 0;                        // monotonic global barrier

// ---------------- helpers ----------------
__device__ __forceinline__ float gelu_f(float x) {
    return 0.5f * x * (1.0f + erff(x * 0.70710678118654752440f));
}
__device__ __forceinline__ u32 to_tf32(float x) {
    u32 o;
    asm("cvt.rna.tf32.f32 %0, %1;" : "=r"(o) : "f"(x));
    return o;
}
__device__ __forceinline__ void mma8(float& d0, float& d1, float& d2, float& d3,
                                     u32 a0, u32 a1, u32 a2, u32 a3,
                                     u32 b0, u32 b1) {
    asm volatile("mma.sync.aligned.m16n8k8.row.col.f32.tf32.tf32.f32 "
                 "{%0,%1,%2,%3}, {%4,%5,%6,%7}, {%8,%9}, {%0,%1,%2,%3};"
                 : "+f"(d0), "+f"(d1), "+f"(d2), "+f"(d3)
                 : "r"(a0), "r"(a1), "r"(a2), "r"(a3), "r"(b0), "r"(b1));
}
__device__ __forceinline__ void barg(int id) {
    asm volatile("bar.sync %0, 256;" :: "r"(id) : "memory");
}

// smem layout (phase 2); phase 1 reuses the first 80KB as GEMM buffers
#define OFF_W  0u        // 139264 : W fragments
#define OFF_X  139264u   // 2 x 32768 : X branch fragments (double buffer)
#define OFF_XS 204800u   // 8192 : X stats fragments
#define OFF_HS 212992u   // 4096 : g_Hc staging
#define OFF_LS 217088u   // 8192 : logit exchange [4][128][4]
#define OFF_W2 225280u   // 2048 : W2
#define SM_TOT 227328u

// ---------------------------------------------------------------------------
// fused kernel: phase 1 = prep (GEMM + weight build), global barrier,
//               phase 2 = persistent gate (verbatim from R14 pass).
// ---------------------------------------------------------------------------
__global__ __launch_bounds__(512, 1) void fused_gate(
    const float* __restrict__ A,   const float* __restrict__ W1,
    const float* __restrict__ b1,
    const float* __restrict__ br0, const float* __restrict__ br1,
    const float* __restrict__ br2, const float* __restrict__ br3,
    const float* __restrict__ W2,  const float* __restrict__ b2,
    const float* __restrict__ eps, const float* __restrict__ temp,
    float* __restrict__ out)
{
    extern __shared__ char sm[];
    const int tid = threadIdx.x;

    // ======================= PHASE 1: prep =======================
    if (blockIdx.x >= 128) {
        // ---- weight-build strip: units u = bid-128 (+20, +40) ----
        u32* dst = (u32*)g_Wt;
#pragma unroll 1
        for (int u = blockIdx.x - 128; u < 45; u += 20) {
            if (u < 32) {
                int kb = u;
#pragma unroll
                for (int i = 0; i < 2; i++) {
                    int gi = tid + i * 512;       // 0..1023
                    int kl = gi >> 7, n = gi & 127;
                    float v = W1[(size_t)(1792 + kb * 8 + kl) * 128 + n];
                    dst[(u32)((kb * 8 + (n >> 4)) * 128
                        + ((n & 7) * 4 + (kl & 3)) * 4 + ((n >> 3) & 1) * 2 + (kl >> 2))]
                        = to_tf32(v);
                }
            } else if (u < 44) {
                int s = u - 32;
                int n = tid >> 2, q = tid & 3;    // 4-way row split
                const float* p = W1 + (size_t)(1024 + s * 64 + q * 16) * 128 + n;
                float acc = 0.f;
#pragma unroll
                for (int r = 0; r < 16; r++) acc += p[(size_t)r * 128];
                acc += __shfl_xor_sync(0xffffffffu, acc, 1);
                acc += __shfl_xor_sync(0xffffffffu, acc, 2);
                if (q == 0) {
                    int kb = 32 + (s >> 3), kl = s & 7;
                    dst[(u32)((kb * 8 + (n >> 4)) * 128
                        + ((n & 7) * 4 + (kl & 3)) * 4 + ((n >> 3) & 1) * 2 + (kl >> 2))]
                        = to_tf32(acc);
                }
            } else {
                int sk = 12 + (tid >> 7), n = tid & 127;   // 512 entries
                int kl = sk & 7;                  // 4..7
                dst[(u32)((33 * 8 + (n >> 4)) * 128
                    + ((n & 7) * 4 + (kl & 3)) * 4 + ((n >> 3) & 1) * 2 + 1)] = 0u;
            }
        }
    } else {
        // ---- GEMM: g_Hc = hidden @ W1[0:1024] + b1 (split-K dual pipelines) ----
        u32* smw = (u32*)sm;
        u32* Af = smw;          // [2][2048] (buffer = group)
        u32* Bf = smw + 4096;   // [2][8192]

        const int kg   = tid >> 8;        // group 0/1
        const int gtid = tid & 255;
        const int m0 = blockIdx.x * 32;
        const int lane = gtid & 31, warp = gtid >> 5;
        const int mg = warp & 1, ng = warp >> 1;

        const int ar = gtid >> 3, akb = gtid & 7;
        const int arl = ar & 7, arh = ((ar & 15) >= 8) ? 1 : 0;
        const int afrag = akb * 2 + (ar >> 4);
        const u32 aswz = (u32)((arl << 2) ^ (akb << 2));
        const float* Ag = A + (size_t)(m0 + ar) * HIDD + akb * 8;

        const int bk = gtid >> 2, bn0 = (gtid & 3) * 32;
        const int bkb = bk >> 3, bkl = bk & 7;
        const int bw = (bkl >= 4) ? 1 : 0, bkq = bkl & 3;
        const float* Bg = W1 + (size_t)bk * OUTC + bn0;

        const u32 ard = (u32)((lane * 4) ^ ((lane >> 2) << 2));

        float d[4][4];
#pragma unroll
        for (int i = 0; i < 4; i++)
#pragma unroll
            for (int j = 0; j < 4; j++) d[i][j] = 0.f;

        float av[8];
        float bv[32];

#define LDGA(CK) do {                                                  \
    float4 t0 = *(const float4*)(Ag + (CK) * 64);                      \
    float4 t1 = *(const float4*)(Ag + (CK) * 64 + 4);                  \
    av[0]=t0.x; av[1]=t0.y; av[2]=t0.z; av[3]=t0.w;                    \
    av[4]=t1.x; av[5]=t1.y; av[6]=t1.z; av[7]=t1.w;                    \
} while (0)

#define LDGB(CK) do {                                                  \
    _Pragma("unroll")                                                  \
    for (int g_ = 0; g_ < 8; g_++) {                                   \
        float4 t_ = *(const float4*)(Bg + (size_t)(CK) * 64 * OUTC + g_ * 4); \
        bv[g_*4+0]=t_.x; bv[g_*4+1]=t_.y; bv[g_*4+2]=t_.z; bv[g_*4+3]=t_.w;  \
    }                                                                  \
} while (0)

#define STORE(BUF) do {                                                \
    _Pragma("unroll")                                                  \
    for (int j_ = 0; j_ < 8; j_++) {                                   \
        u32 wi_ = (u32)(arl * 16 + (j_ & 3) * 4 + arh + ((j_ >= 4) ? 2 : 0)) ^ aswz; \
        Af[(BUF) * 2048 + afrag * 128 + wi_] = to_tf32(av[j_]);        \
    }                                                                  \
    _Pragma("unroll")                                                  \
    for (int j_ = 0; j_ < 32; j_++) {                                  \
        int n_ = bn0 + j_;                                             \
        int nb_ = n_ >> 3;                                             \
        u32 x_ = (u32)((((n_ & 7) * 4 + bkq) * 2 + bw)) ^ (u32)(nb_ << 1); \
        Bf[(BUF) * 8192 + (bkb * 16 + nb_) * 64 + x_] = to_tf32(bv[j_]); \
    }                                                                  \
} while (0)

#define MMACHUNK(BUF) do {                                             \
    _Pragma("unroll")                                                  \
    for (int kb_ = 0; kb_ < 8; kb_++) {                                \
        uint4 Av_ = *(const uint4*)&Af[(BUF) * 2048 + (kb_ * 2 + mg) * 128 \
                                       + (ard ^ (u32)(kb_ << 2))];     \
        _Pragma("unroll")                                              \
        for (int q_ = 0; q_ < 4; q_++) {                               \
            int nb_ = ng * 4 + q_;                                     \
            uint2 Bv_ = *(const uint2*)&Bf[(BUF) * 8192 + (kb_ * 16 + nb_) * 64 \
                                           + (u32)((lane * 2) ^ (nb_ << 1))];   \
            mma8(d[q_][0], d[q_][1], d[q_][2], d[q_][3],               \
                 Av_.x, Av_.y, Av_.z, Av_.w, Bv_.x, Bv_.y);            \
        }                                                              \
    }                                                                  \
} while (0)

        // group kg handles chunks kg, kg+2, ..., 14+kg
        LDGA(kg); LDGB(kg);
        STORE(kg);
        barg(1 + kg);

#pragma unroll 1
        for (int c = kg; c < 16; c += 2) {
            if (c + 2 < 16) { LDGA(c + 2); LDGB(c + 2); }
            MMACHUNK(kg);
            if (c + 2 < 16) {
                barg(1 + kg);
                STORE(kg);
                barg(1 + kg);
            }
        }

        // cross-group reduction
        __syncthreads();
        if (kg == 1) {
            float4* ps = (float4*)smw;
#pragma unroll
            for (int q = 0; q < 4; q++)
                ps[gtid * 4 + q] = make_float4(d[q][0], d[q][1], d[q][2], d[q][3]);
        }
        __syncthreads();
        if (kg == 0) {
            const float4* ps = (const float4*)smw;
#pragma unroll
            for (int q = 0; q < 4; q++) {
                float4 o = ps[gtid * 4 + q];
                d[q][0] += o.x; d[q][1] += o.y; d[q][2] += o.z; d[q][3] += o.w;
            }
            const int row0 = m0 + mg * 16 + (lane >> 2);
            const int col0 = ng * 32 + (lane & 3) * 2;
#pragma unroll
            for (int q = 0; q < 4; q++) {
                int col = col0 + q * 8;
                float2 bb = *(const float2*)(b1 + col);
                *(float2*)&g_Hc[(size_t)row0 * OUTC + col] =
                    make_float2(d[q][0] + bb.x, d[q][1] + bb.y);
                *(float2*)&g_Hc[(size_t)(row0 + 8) * OUTC + col] =
                    make_float2(d[q][2] + bb.x, d[q][3] + bb.y);
            }
        }
#undef LDGA
#undef LDGB
#undef STORE
#undef MMACHUNK
    }

    // ======================= GLOBAL BARRIER =======================
    __threadfence();
    __syncthreads();
    if (tid == 0) {
        u32 old = atomicAdd(&g_count, 1u);
        u32 target = (old / 148u + 1u) * 148u;
        while (*(volatile u32*)&g_count < target) {}
    }
    __syncthreads();
    __threadfence();

    // ======================= PHASE 2: gate =======================
    const int lane = tid & 31, warp = tid >> 5;
    const int mp = warp >> 2, nq = warp & 3;

    {
        const float4* s = (const float4*)g_Wt;
        float4* d = (float4*)(sm + OFF_W);
        for (int i = tid; i < 8704; i += 512) d[i] = s[i];
    }
    {
        float4* d = (float4*)(sm + OFF_XS);
        for (int i = tid; i < 512; i += 512) d[i] = make_float4(0.f, 0.f, 0.f, 0.f);
    }
    {
        float* d = (float*)(sm + OFF_W2);
        d[tid] = W2[tid & 511];
    }
    const float4 b2v = *(const float4*)b2;
    float it_h = 1.f;
    float4 fl_h = make_float4(0.f, 0.f, 0.f, 0.f);
    if (tid < 128) {
        int head = tid & 15;
        it_h = 1.f / fminf(fmaxf(temp[head], 0.2f), 10.0f);
        float4 ef = *(const float4*)(eps + head * 4);
        fl_h.x = fminf(fmaxf(ef.x, 1e-7f), 0.1f);
        fl_h.y = fminf(fmaxf(ef.y, 1e-7f), 0.1f);
        fl_h.z = fminf(fmaxf(ef.z, 1e-7f), 0.1f);
        fl_h.w = fminf(fmaxf(ef.w, 1e-7f), 0.1f);
    }
    __syncthreads();

    const int lm = tid >> 2, lq = tid & 3;
    const int lmt = lm >> 4;
    const int lr  = lm & 15;
    const int rlow = lr & 7, rhi = (lr >= 8) ? 1 : 0;
    const int swzr = rlow << 2;
    const int swz_l = (lane * 4) ^ ((lane >> 2) << 2);
    const int tig = lane & 3, gid = lane >> 2;

    float4 v[4];
    int tt = blockIdx.x;
    {
        const float* src = br0 + (size_t)(tt * 8 + lmt) * 1024 + lr * 64 + lq * 16;
#pragma unroll
        for (int j = 0; j < 4; j++) v[j] = *(const float4*)(src + j * 4);
    }

    for (; tt < 512; tt += 148) {
        const int base = tt * 8;

        if (tid < 256) {
            const float4* s = (const float4*)(g_Hc + (size_t)base * 128);
            ((float4*)(sm + OFF_HS))[tid] = s[tid];
        }

        float dd[2][4][4];
#pragma unroll
        for (int mt = 0; mt < 2; mt++)
#pragma unroll
            for (int nb = 0; nb < 4; nb++)
#pragma unroll
                for (int c = 0; c < 4; c++) dd[mt][nb][c] = 0.f;

#pragma unroll 1
        for (int p = 0; p < 4; p++) {
            float s = 0.f, q2 = 0.f, mx = -INFINITY;
#pragma unroll
            for (int j = 0; j < 4; j++) {
                s  += (v[j].x + v[j].y) + (v[j].z + v[j].w);
                q2 += v[j].x * v[j].x + v[j].y * v[j].y
                    + v[j].z * v[j].z + v[j].w * v[j].w;
                mx = fmaxf(mx, fmaxf(fmaxf(v[j].x, v[j].y), fmaxf(v[j].z, v[j].w)));
            }
            s  += __shfl_xor_sync(0xffffffffu, s, 1);
            q2 += __shfl_xor_sync(0xffffffffu, q2, 1);
            mx  = fmaxf(mx, __shfl_xor_sync(0xffffffffu, mx, 1));
            s  += __shfl_xor_sync(0xffffffffu, s, 2);
            q2 += __shfl_xor_sync(0xffffffffu, q2, 2);
            mx  = fmaxf(mx, __shfl_xor_sync(0xffffffffu, mx, 2));

            {
                u32* xb = (u32*)(sm + OFF_X) + (p & 1) * 8192 + lmt * 1024;
                const float* vf = (const float*)v;
#pragma unroll
                for (int j = 0; j < 16; j++) {
                    int kbl = lq * 2 + (j >> 3);
                    int kp  = j & 7;
                    int off = (rlow * 16 + (kp & 3) * 4 + rhi + ((kp >= 4) ? 2 : 0)) ^ swzr;
                    xb[kbl * 128 + off] = to_tf32(vf[j]);
                }
                if (lq == 0) {
                    float st0 = s * (1.f / 64.f);
                    float st1 = sqrtf(fmaxf(q2 * (1.f / 64.f), 1e-8f));
                    float st2 = mx;
                    u32* xs = (u32*)(sm + OFF_XS) + lmt * 256;
#pragma unroll
                    for (int t2 = 0; t2 < 3; t2++) {
                        int sk = p * 3 + t2;
                        int kbs = sk >> 3, kp = sk & 7;
                        int off = (rlow * 16 + (kp & 3) * 4 + rhi + ((kp >= 4) ? 2 : 0)) ^ swzr;
                        float sv = (t2 == 0) ? st0 : (t2 == 1) ? st1 : st2;
                        xs[kbs * 128 + off] = to_tf32(sv);
                    }
                }
            }
            __syncthreads();

            if (p < 3) {
                const float* bp = (p == 0) ? br1 : (p == 1) ? br2 : br3;
                const float* src = bp + (size_t)(base + lmt) * 1024 + lr * 64 + lq * 16;
#pragma unroll
                for (int j = 0; j < 4; j++) v[j] = *(const float4*)(src + j * 4);
            }

            {
                const char* xbase = sm + OFF_X + (p & 1) * 32768u;
                const char* ab = xbase + (u32)(2 * mp) * 4096u + (u32)swz_l * 4u;
#pragma unroll
                for (int kbl = 0; kbl < 8; kbl++) {
                    const char* wk = sm + OFF_W
                                   + (u32)(((p * 8 + kbl) * 8 + 2 * nq) * 512)
                                   + (u32)lane * 16u;
                    uint4 B0 = *(const uint4*)(wk);
                    uint4 B1 = *(const uint4*)(wk + 512);
                    uint4 A0 = *(const uint4*)(ab + kbl * 512);
                    mma8(dd[0][0][0], dd[0][0][1], dd[0][0][2], dd[0][0][3],
                         A0.x, A0.y, A0.z, A0.w, B0.x, B0.y);
                    mma8(dd[0][1][0], dd[0][1][1], dd[0][1][2], dd[0][1][3],
                         A0.x, A0.y, A0.z, A0.w, B0.z, B0.w);
                    mma8(dd[0][2][0], dd[0][2][1], dd[0][2][2], dd[0][2][3],
                         A0.x, A0.y, A0.z, A0.w, B1.x, B1.y);
                    mma8(dd[0][3][0], dd[0][3][1], dd[0][3][2], dd[0][3][3],
                         A0.x, A0.y, A0.z, A0.w, B1.z, B1.w);
                    uint4 A1 = *(const uint4*)(ab + 4096 + kbl * 512);
                    mma8(dd[1][0][0], dd[1][0][1], dd[1][0][2], dd[1][0][3],
                         A1.x, A1.y, A1.z, A1.w, B0.x, B0.y);
                    mma8(dd[1][1][0], dd[1][1][1], dd[1][1][2], dd[1][1][3],
                         A1.x, A1.y, A1.z, A1.w, B0.z, B0.w);
                    mma8(dd[1][2][0], dd[1][2][1], dd[1][2][2], dd[1][2][3],
                         A1.x, A1.y, A1.z, A1.w, B1.x, B1.y);
                    mma8(dd[1][3][0], dd[1][3][1], dd[1][3][2], dd[1][3][3],
                         A1.x, A1.y, A1.z, A1.w, B1.z, B1.w);
                }
                if (p == 3) {
                    const char* sb = sm + OFF_XS + (u32)(2 * mp) * 1024u
                                   + (u32)swz_l * 4u;
#pragma unroll
                    for (int kbs = 0; kbs < 2; kbs++) {
                        const char* wk = sm + OFF_W
                                       + (u32)((((32 + kbs) * 8) + 2 * nq) * 512)
                                       + (u32)lane * 16u;
                        uint4 B0 = *(const uint4*)(wk);
                        uint4 B1 = *(const uint4*)(wk + 512);
                        uint4 A0 = *(const uint4*)(sb + kbs * 512);
                        mma8(dd[0][0][0], dd[0][0][1], dd[0][0][2], dd[0][0][3],
                             A0.x, A0.y, A0.z, A0.w, B0.x, B0.y);
                        mma8(dd[0][1][0], dd[0][1][1], dd[0][1][2], dd[0][1][3],
                             A0.x, A0.y, A0.z, A0.w, B0.z, B0.w);
                        mma8(dd[0][2][0], dd[0][2][1], dd[0][2][2], dd[0][2][3],
                             A0.x, A0.y, A0.z, A0.w, B1.x, B1.y);
                        mma8(dd[0][3][0], dd[0][3][1], dd[0][3][2], dd[0][3][3],
                             A0.x, A0.y, A0.z, A0.w, B1.z, B1.w);
                        uint4 A1 = *(const uint4*)(sb + 1024 + kbs * 512);
                        mma8(dd[1][0][0], dd[1][0][1], dd[1][0][2], dd[1][0][3],
                             A1.x, A1.y, A1.z, A1.w, B0.x, B0.y);
                        mma8(dd[1][1][0], dd[1][1][1], dd[1][1][2], dd[1][1][3],
                             A1.x, A1.y, A1.z, A1.w, B0.z, B0.w);
                        mma8(dd[1][2][0], dd[1][2][1], dd[1][2][2], dd[1][2][3],
                             A1.x, A1.y, A1.z, A1.w, B1.x, B1.y);
                        mma8(dd[1][3][0], dd[1][3][1], dd[1][3][2], dd[1][3][3],
                             A1.x, A1.y, A1.z, A1.w, B1.z, B1.w);
                    }
                }
            }
        } // p loop

        if (tt + 148 < 512) {
            const float* src = br0 + (size_t)((tt + 148) * 8 + lmt) * 1024
                             + lr * 64 + lq * 16;
#pragma unroll
            for (int j = 0; j < 4; j++) v[j] = *(const float4*)(src + j * 4);
        }

        // ---- epilogue ----
        const float* Hsf = (const float*)(sm + OFF_HS);
        const float* W2s = (const float*)(sm + OFF_W2);
#pragma unroll
        for (int mt = 0; mt < 2; mt++) {
            float LA[4] = {0.f, 0.f, 0.f, 0.f}, LB[4] = {0.f, 0.f, 0.f, 0.f};
            const float* hrow = Hsf + (2 * mp + mt) * 128;
#pragma unroll
            for (int nbl = 0; nbl < 4; nbl++) {
                int n0 = (nq * 4 + nbl) * 8 + tig * 2;
                float4 wa = *(const float4*)&W2s[n0 * 4];
                float4 wb = *(const float4*)&W2s[n0 * 4 + 4];
                float2 hc = *(const float2*)&hrow[n0];
                float h00 = gelu_f(dd[mt][nbl][0] + hc.x);
                float h01 = gelu_f(dd[mt][nbl][1] + hc.y);
                float h10 = gelu_f(dd[mt][nbl][2] + hc.x);
                float h11 = gelu_f(dd[mt][nbl][3] + hc.y);
                LA[0] += h00 * wa.x + h01 * wb.x; LA[1] += h00 * wa.y + h01 * wb.y;
                LA[2] += h00 * wa.z + h01 * wb.z; LA[3] += h00 * wa.w + h01 * wb.w;
                LB[0] += h10 * wa.x + h11 * wb.x; LB[1] += h10 * wa.y + h11 * wb.y;
                LB[2] += h10 * wa.z + h11 * wb.z; LB[3] += h10 * wa.w + h11 * wb.w;
            }
#pragma unroll
            for (int off = 1; off <= 2; off <<= 1) {
#pragma unroll
                for (int q = 0; q < 4; q++) {
                    LA[q] += __shfl_xor_sync(0xffffffffu, LA[q], off);
                    LB[q] += __shfl_xor_sync(0xffffffffu, LB[q], off);
                }
            }
            if (tig == 0) {
                float4* Ls = (float4*)(sm + OFF_LS);
                int r = (2 * mp + mt) * 16 + gid;
                Ls[nq * 128 + r]     = make_float4(LA[0], LA[1], LA[2], LA[3]);
                Ls[nq * 128 + r + 8] = make_float4(LB[0], LB[1], LB[2], LB[3]);
            }
        }
        __syncthreads();
        if (tid < 128) {
            const float4* Ls = (const float4*)(sm + OFF_LS);
            float4 p0 = Ls[tid], p1 = Ls[128 + tid];
            float4 p2 = Ls[256 + tid], p3 = Ls[384 + tid];
            float l0 = p0.x + p1.x + p2.x + p3.x + b2v.x;
            float l1 = p0.y + p1.y + p2.y + p3.y + b2v.y;
            float l2 = p0.z + p1.z + p2.z + p3.z + b2v.z;
            float l3 = p0.w + p1.w + p2.w + p3.w + b2v.w;
            float s0 = l0 * it_h, s1 = l1 * it_h, s2 = l2 * it_h, s3 = l3 * it_h;
            float m = fmaxf(fmaxf(s0, s1), fmaxf(s2, s3));
            float e0 = expf(s0 - m), e1 = expf(s1 - m);
            float e2 = expf(s2 - m), e3 = expf(s3 - m);
            float inv = 1.f / (e0 + e1 + e2 + e3);
            float w0 = fmaxf(e0 * inv, fl_h.x);
            float w1 = fmaxf(e1 * inv, fl_h.y);
            float w2_ = fmaxf(e2 * inv, fl_h.z);
            float w3 = fmaxf(e3 * inv, fl_h.w);
            float inv2 = 1.f / (w0 + w1 + w2_ + w3);
            int bl = tid >> 4, head = tid & 15;
            *(float4*)(out + (size_t)(base + bl) * 64 + head * 4) =
                make_float4(w0 * inv2, w1 * inv2, w2_ * inv2, w3 * inv2);
        }
        __syncthreads();
    }
}

// ---------------------------------------------------------------------------
extern "C" void kernel_launch(void* const* d_in, const int* in_sizes, int n_in,
                              void* d_out, int out_size) {
    (void)in_sizes; (void)n_in; (void)out_size;
    const float* hidden = (const float*)d_in[0];
    const float* b0     = (const float*)d_in[1];
    const float* b1br   = (const float*)d_in[2];
    const float* b2br   = (const float*)d_in[3];
    const float* b3br   = (const float*)d_in[4];
    const float* W1     = (const float*)d_in[5];
    const float* b1     = (const float*)d_in[6];
    const float* W2     = (const float*)d_in[7];
    const float* b2     = (const float*)d_in[8];
    const float* eps    = (const float*)d_in[9];
    const float* temp   = (const float*)d_in[10];
    float* out = (float*)d_out;

    cudaFuncSetAttribute(fused_gate, cudaFuncAttributeMaxDynamicSharedMemorySize,
                         (int)SM_TOT);

    fused_gate<<<148, 512, SM_TOT>>>(hidden, W1, b1, b0, b1br, b2br, b3br,
                                     W2, b2, eps, temp, out);
}

// round 16
// speedup vs baseline: 1.2091x; 1.2091x over previous
#include <cuda_runtime.h>
#include <math.h>
#include <stdint.h>

#define NBL  4096
#define HIDD 1024
#define OUTC 128
typedef unsigned long long ull;
typedef uint32_t u32;

// ---------------- device scratch (allocation-free rule) ----------------
__device__ __align__(16) float g_Hc[NBL * OUTC];   // hidden @ W1[0:1024] + b1
__device__ __align__(16) float g_Wt[34816];        // gate W fragments (f16 pairs)

// ---------------- helpers ----------------
__device__ __forceinline__ float gelu_f(float x) {
    return 0.5f * x * (1.0f + erff(x * 0.70710678118654752440f));
}
__device__ __forceinline__ u32 to_tf32(float x) {
    u32 o;
    asm("cvt.rna.tf32.f32 %0, %1;" : "=r"(o) : "f"(x));
    return o;
}
__device__ __forceinline__ u32 pkf16(float lo, float hi) {
    u32 d;
    asm("cvt.rn.f16x2.f32 %0, %1, %2;" : "=r"(d) : "f"(hi), "f"(lo));
    return d;
}
// tf32 k8 mma (prep)
__device__ __forceinline__ void mma8(float& d0, float& d1, float& d2, float& d3,
                                     u32 a0, u32 a1, u32 a2, u32 a3,
                                     u32 b0, u32 b1) {
    asm volatile("mma.sync.aligned.m16n8k8.row.col.f32.tf32.tf32.f32 "
                 "{%0,%1,%2,%3}, {%4,%5,%6,%7}, {%8,%9}, {%0,%1,%2,%3};"
                 : "+f"(d0), "+f"(d1), "+f"(d2), "+f"(d3)
                 : "r"(a0), "r"(a1), "r"(a2), "r"(a3), "r"(b0), "r"(b1));
}
// f16 k16 mma (gate) — same operand shapes, k granularity = pairs
__device__ __forceinline__ void mma16(float& d0, float& d1, float& d2, float& d3,
                                      u32 a0, u32 a1, u32 a2, u32 a3,
                                      u32 b0, u32 b1) {
    asm volatile("mma.sync.aligned.m16n8k16.row.col.f32.f16.f16.f32 "
                 "{%0,%1,%2,%3}, {%4,%5,%6,%7}, {%8,%9}, {%0,%1,%2,%3};"
                 : "+f"(d0), "+f"(d1), "+f"(d2), "+f"(d3)
                 : "r"(a0), "r"(a1), "r"(a2), "r"(a3), "r"(b0), "r"(b1));
}
__device__ __forceinline__ void barg(int id) {
    asm volatile("bar.sync %0, 256;" :: "r"(id) : "memory");
}

// ---------------------------------------------------------------------------
// prep_mma (512 threads, grid 148):
//  blocks 0..127   : g_Hc = hidden @ W1[0:1024] + b1 (tf32 mma, split-K; R14)
//  blocks 128..147 : gate-W build units u (stride 20, u < 23), f16 pair layout:
//    word(K, p4, n) = (K*8 + (n>>4))*128 + ((n&7)*4 + (p4&3))*4
//                   + ((n>>3)&1)*2 + (p4>>2)
//    value = pack_f16( Wsrc(K*16 + 2*p4, n), Wsrc(K*16 + 2*p4 + 1, n) )
//    u in [0,16)  : branch K=u (rows W1[1792 + K*16 + ...])
//    u in [16,22) : stat pair v=u-16 -> (s=2v, 2v+1) column sums, K=16, p4=v
//    u == 22      : zero pads K=16, p4 = 6,7
// ---------------------------------------------------------------------------
#define PREP_SMEM (20480 * 4)

__global__ __launch_bounds__(512) void prep_mma(const float* __restrict__ A,
                                                const float* __restrict__ W1,
                                                const float* __restrict__ b1) {
    const int tid = threadIdx.x;

    if (blockIdx.x >= 128) {
        u32* dst = (u32*)g_Wt;
#pragma unroll 1
        for (int u = blockIdx.x - 128; u < 23; u += 20) {
            if (u < 16) {
                int K = u;
#pragma unroll
                for (int i = 0; i < 2; i++) {
                    int gi = tid + i * 512;       // 0..1023
                    int p4 = gi >> 7, n = gi & 127;
                    float f0 = W1[(size_t)(1792 + K * 16 + p4 * 2) * 128 + n];
                    float f1 = W1[(size_t)(1792 + K * 16 + p4 * 2 + 1) * 128 + n];
                    dst[(u32)((K * 8 + (n >> 4)) * 128
                        + ((n & 7) * 4 + (p4 & 3)) * 4 + ((n >> 3) & 1) * 2 + (p4 >> 2))]
                        = pkf16(f0, f1);
                }
            } else if (u < 22) {
                int v = u - 16;                   // pair (s=2v, 2v+1)
                int n = tid >> 2, q = tid & 3;
                const float* p0 = W1 + (size_t)(1024 + (2 * v) * 64 + q * 16) * 128 + n;
                const float* p1 = W1 + (size_t)(1024 + (2 * v + 1) * 64 + q * 16) * 128 + n;
                float a0 = 0.f, a1 = 0.f;
#pragma unroll
                for (int r = 0; r < 16; r++) {
                    a0 += p0[(size_t)r * 128];
                    a1 += p1[(size_t)r * 128];
                }
                a0 += __shfl_xor_sync(0xffffffffu, a0, 1);
                a0 += __shfl_xor_sync(0xffffffffu, a0, 2);
                a1 += __shfl_xor_sync(0xffffffffu, a1, 1);
                a1 += __shfl_xor_sync(0xffffffffu, a1, 2);
                if (q == 0) {
                    dst[(u32)((16 * 8 + (n >> 4)) * 128
                        + ((n & 7) * 4 + (v & 3)) * 4 + ((n >> 3) & 1) * 2 + (v >> 2))]
                        = pkf16(a0, a1);
                }
            } else {
                if (tid < 256) {
                    int p4 = 6 + (tid >> 7), n = tid & 127;
                    dst[(u32)((16 * 8 + (n >> 4)) * 128
                        + ((n & 7) * 4 + (p4 & 3)) * 4 + ((n >> 3) & 1) * 2 + (p4 >> 2))]
                        = 0u;
                }
            }
        }
        return;
    }

    // ---- GEMM (verbatim R14 split-K tf32) ----
    extern __shared__ u32 smw[];
    u32* Af = smw;
    u32* Bf = smw + 4096;

    const int kg   = tid >> 8;
    const int gtid = tid & 255;
    const int m0 = blockIdx.x * 32;
    const int lane = gtid & 31, warp = gtid >> 5;
    const int mg = warp & 1, ng = warp >> 1;

    const int ar = gtid >> 3, akb = gtid & 7;
    const int arl = ar & 7, arh = ((ar & 15) >= 8) ? 1 : 0;
    const int afrag = akb * 2 + (ar >> 4);
    const u32 aswz = (u32)((arl << 2) ^ (akb << 2));
    const float* Ag = A + (size_t)(m0 + ar) * HIDD + akb * 8;

    const int bk = gtid >> 2, bn0 = (gtid & 3) * 32;
    const int bkb = bk >> 3, bkl = bk & 7;
    const int bw = (bkl >= 4) ? 1 : 0, bkq = bkl & 3;
    const float* Bg = W1 + (size_t)bk * OUTC + bn0;

    const u32 ard = (u32)((lane * 4) ^ ((lane >> 2) << 2));

    float d[4][4];
#pragma unroll
    for (int i = 0; i < 4; i++)
#pragma unroll
        for (int j = 0; j < 4; j++) d[i][j] = 0.f;

    float av[8];
    float bv[32];

#define LDGA(CK) do {                                                  \
    float4 t0 = *(const float4*)(Ag + (CK) * 64);                      \
    float4 t1 = *(const float4*)(Ag + (CK) * 64 + 4);                  \
    av[0]=t0.x; av[1]=t0.y; av[2]=t0.z; av[3]=t0.w;                    \
    av[4]=t1.x; av[5]=t1.y; av[6]=t1.z; av[7]=t1.w;                    \
} while (0)

#define LDGB(CK) do {                                                  \
    _Pragma("unroll")                                                  \
    for (int g_ = 0; g_ < 8; g_++) {                                   \
        float4 t_ = *(const float4*)(Bg + (size_t)(CK) * 64 * OUTC + g_ * 4); \
        bv[g_*4+0]=t_.x; bv[g_*4+1]=t_.y; bv[g_*4+2]=t_.z; bv[g_*4+3]=t_.w;  \
    }                                                                  \
} while (0)

#define STORE(BUF) do {                                                \
    _Pragma("unroll")                                                  \
    for (int j_ = 0; j_ < 8; j_++) {                                   \
        u32 wi_ = (u32)(arl * 16 + (j_ & 3) * 4 + arh + ((j_ >= 4) ? 2 : 0)) ^ aswz; \
        Af[(BUF) * 2048 + afrag * 128 + wi_] = to_tf32(av[j_]);        \
    }                                                                  \
    _Pragma("unroll")                                                  \
    for (int j_ = 0; j_ < 32; j_++) {                                  \
        int n_ = bn0 + j_;                                             \
        int nb_ = n_ >> 3;                                             \
        u32 x_ = (u32)((((n_ & 7) * 4 + bkq) * 2 + bw)) ^ (u32)(nb_ << 1); \
        Bf[(BUF) * 8192 + (bkb * 16 + nb_) * 64 + x_] = to_tf32(bv[j_]); \
    }                                                                  \
} while (0)

#define MMACHUNK(BUF) do {                                             \
    _Pragma("unroll")                                                  \
    for (int kb_ = 0; kb_ < 8; kb_++) {                                \
        uint4 Av_ = *(const uint4*)&Af[(BUF) * 2048 + (kb_ * 2 + mg) * 128 \
                                       + (ard ^ (u32)(kb_ << 2))];     \
        _Pragma("unroll")                                              \
        for (int q_ = 0; q_ < 4; q_++) {                               \
            int nb_ = ng * 4 + q_;                                     \
            uint2 Bv_ = *(const uint2*)&Bf[(BUF) * 8192 + (kb_ * 16 + nb_) * 64 \
                                           + (u32)((lane * 2) ^ (nb_ << 1))];   \
            mma8(d[q_][0], d[q_][1], d[q_][2], d[q_][3],               \
                 Av_.x, Av_.y, Av_.z, Av_.w, Bv_.x, Bv_.y);            \
        }                                                              \
    }                                                                  \
} while (0)

    LDGA(kg); LDGB(kg);
    STORE(kg);
    barg(1 + kg);

#pragma unroll 1
    for (int c = kg; c < 16; c += 2) {
        if (c + 2 < 16) { LDGA(c + 2); LDGB(c + 2); }
        MMACHUNK(kg);
        if (c + 2 < 16) {
            barg(1 + kg);
            STORE(kg);
            barg(1 + kg);
        }
    }

    __syncthreads();
    if (kg == 1) {
        float4* ps = (float4*)smw;
#pragma unroll
        for (int q = 0; q < 4; q++)
            ps[gtid * 4 + q] = make_float4(d[q][0], d[q][1], d[q][2], d[q][3]);
    }
    __syncthreads();
    if (kg == 0) {
        const float4* ps = (const float4*)smw;
#pragma unroll
        for (int q = 0; q < 4; q++) {
            float4 o = ps[gtid * 4 + q];
            d[q][0] += o.x; d[q][1] += o.y; d[q][2] += o.z; d[q][3] += o.w;
        }
        const int row0 = m0 + mg * 16 + (lane >> 2);
        const int col0 = ng * 32 + (lane & 3) * 2;
#pragma unroll
        for (int q = 0; q < 4; q++) {
            int col = col0 + q * 8;
            float2 bb = *(const float2*)(b1 + col);
            *(float2*)&g_Hc[(size_t)row0 * OUTC + col] =
                make_float2(d[q][0] + bb.x, d[q][1] + bb.y);
            *(float2*)&g_Hc[(size_t)(row0 + 8) * OUTC + col] =
                make_float2(d[q][2] + bb.x, d[q][3] + bb.y);
        }
    }
}

// ---------------------------------------------------------------------------
// gate_mma: persistent f16 m16n8k16 gate kernel. 512 threads.
// Tile M=128, N=128, K = 17 kb16 (16 branch + 1 stats[12 real + 4 pad]).
// Warp (mp=warp>>2, nq=warp&3): M32 x N32; per kb16: 2 A + 2 B LDS.128, 8 mma.
// ---------------------------------------------------------------------------
#define OFF_W    0u        // 69632 : W fragments (17408 words)
#define OFF_X    69632u    // 2 x 16384 : X branch fragments (double buffer)
#define OFF_XS   102400u   // 4096 : X stats fragments [8 mt][128 w]
#define OFF_XSTG 106496u   // 6144 : stats staging [8 mt][16 r][12] f32
#define OFF_HS   112640u   // 4096 : g_Hc staging
#define OFF_LS   116736u   // 8192 : logit exchange [4][128][4]
#define OFF_W2   124928u   // 2048 : W2
#define SM_TOT   126976u

__global__ __launch_bounds__(512, 1) void gate_mma(
    const float* __restrict__ br0, const float* __restrict__ br1,
    const float* __restrict__ br2, const float* __restrict__ br3,
    const float* __restrict__ W2,  const float* __restrict__ b2,
    const float* __restrict__ eps, const float* __restrict__ temp,
    float* __restrict__ out)
{
    extern __shared__ char sm[];
    const int tid  = threadIdx.x;
    const int lane = tid & 31, warp = tid >> 5;
    const int mp = warp >> 2, nq = warp & 3;

    {   // W fragments: 17408 words = 4352 float4
        const float4* s = (const float4*)g_Wt;
        float4* d = (float4*)(sm + OFF_W);
        for (int i = tid; i < 4352; i += 512) d[i] = s[i];
    }
    {   // zero stats fragment region (1024 words = 256 float4)
        float4* d = (float4*)(sm + OFF_XS);
        if (tid < 256) d[tid] = make_float4(0.f, 0.f, 0.f, 0.f);
    }
    {
        float* d = (float*)(sm + OFF_W2);
        d[tid] = W2[tid & 511];
    }
    const float4 b2v = *(const float4*)b2;
    float it_h = 1.f;
    float4 fl_h = make_float4(0.f, 0.f, 0.f, 0.f);
    if (tid < 128) {
        int head = tid & 15;
        it_h = 1.f / fminf(fmaxf(temp[head], 0.2f), 10.0f);
        float4 ef = *(const float4*)(eps + head * 4);
        fl_h.x = fminf(fmaxf(ef.x, 1e-7f), 0.1f);
        fl_h.y = fminf(fmaxf(ef.y, 1e-7f), 0.1f);
        fl_h.z = fminf(fmaxf(ef.z, 1e-7f), 0.1f);
        fl_h.w = fminf(fmaxf(ef.w, 1e-7f), 0.1f);
    }
    __syncthreads();

    // loader: thread t -> row lm = t>>2 (mtile lmt, head lr), kb16 = lq
    const int lm = tid >> 2, lq = tid & 3;
    const int lmt = lm >> 4;
    const int lr  = lm & 15;
    const int rlow = lr & 7, rhi = (lr >= 8) ? 1 : 0;
    const int swzr = rlow << 2;
    const int swz_l = (lane * 4) ^ ((lane >> 2) << 2);
    const int tig = lane & 3, gid = lane >> 2;

    float4 v[4];
    int tt = blockIdx.x;
    {
        const float* src = br0 + (size_t)(tt * 8 + lmt) * 1024 + lr * 64 + lq * 16;
#pragma unroll
        for (int j = 0; j < 4; j++) v[j] = *(const float4*)(src + j * 4);
    }

    for (; tt < 512; tt += 148) {
        const int base = tt * 8;

        if (tid < 256) {
            const float4* s = (const float4*)(g_Hc + (size_t)base * 128);
            ((float4*)(sm + OFF_HS))[tid] = s[tid];
        }

        float dd[2][4][4];
#pragma unroll
        for (int mt = 0; mt < 2; mt++)
#pragma unroll
            for (int nb = 0; nb < 4; nb++)
#pragma unroll
                for (int c = 0; c < 4; c++) dd[mt][nb][c] = 0.f;

#pragma unroll 1
        for (int p = 0; p < 4; p++) {
            float s = 0.f, q2 = 0.f, mx = -INFINITY;
#pragma unroll
            for (int j = 0; j < 4; j++) {
                s  += (v[j].x + v[j].y) + (v[j].z + v[j].w);
                q2 += v[j].x * v[j].x + v[j].y * v[j].y
                    + v[j].z * v[j].z + v[j].w * v[j].w;
                mx = fmaxf(mx, fmaxf(fmaxf(v[j].x, v[j].y), fmaxf(v[j].z, v[j].w)));
            }
            s  += __shfl_xor_sync(0xffffffffu, s, 1);
            q2 += __shfl_xor_sync(0xffffffffu, q2, 1);
            mx  = fmaxf(mx, __shfl_xor_sync(0xffffffffu, mx, 1));
            s  += __shfl_xor_sync(0xffffffffu, s, 2);
            q2 += __shfl_xor_sync(0xffffffffu, q2, 2);
            mx  = fmaxf(mx, __shfl_xor_sync(0xffffffffu, mx, 2));

            {   // write X fragments: 8 f16-pair words, kb16 = lq
                u32* xb = (u32*)(sm + OFF_X) + (p & 1) * 4096 + lmt * 512 + lq * 128;
                const float* vf = (const float*)v;
#pragma unroll
                for (int j = 0; j < 8; j++) {
                    int off = (rlow * 16 + (j & 3) * 4 + rhi + ((j >= 4) ? 2 : 0)) ^ swzr;
                    xb[off] = pkf16(vf[2 * j], vf[2 * j + 1]);
                }
                if (lq == 0) {   // stats -> unpacked staging
                    float st0 = s * (1.f / 64.f);
                    float st1 = sqrtf(fmaxf(q2 * (1.f / 64.f), 1e-8f));
                    float st2 = mx;
                    float* xstg = (float*)(sm + OFF_XSTG);
                    xstg[(lmt * 16 + lr) * 12 + p * 3 + 0] = st0;
                    xstg[(lmt * 16 + lr) * 12 + p * 3 + 1] = st1;
                    xstg[(lmt * 16 + lr) * 12 + p * 3 + 2] = st2;
                }
            }
            __syncthreads();

            if (p < 3) {
                const float* bp = (p == 0) ? br1 : (p == 1) ? br2 : br3;
                const float* src = bp + (size_t)(base + lmt) * 1024 + lr * 64 + lq * 16;
#pragma unroll
                for (int j = 0; j < 4; j++) v[j] = *(const float4*)(src + j * 4);
            }

            if (p == 3) {   // pack stats pairs into XS fragments
                const float* xstg = (const float*)(sm + OFF_XSTG);
                u32* xsf = (u32*)(sm + OFF_XS);
#pragma unroll 2
                for (int i = tid; i < 768; i += 512) {
                    int mt = i / 96, rem = i % 96;
                    int r = rem / 6, p4 = rem % 6;
                    float lo = xstg[(mt * 16 + r) * 12 + 2 * p4];
                    float hi = xstg[(mt * 16 + r) * 12 + 2 * p4 + 1];
                    int off = ((r & 7) * 16 + (p4 & 3) * 4 + ((r >= 8) ? 1 : 0)
                             + ((p4 >= 4) ? 2 : 0)) ^ ((r & 7) << 2);
                    xsf[mt * 128 + off] = pkf16(lo, hi);
                }
                __syncthreads();
            }

            {
                const char* xbase = sm + OFF_X + (p & 1) * 16384u;
                const char* ab = xbase + (u32)(2 * mp) * 2048u + (u32)swz_l * 4u;
#pragma unroll
                for (int kb = 0; kb < 4; kb++) {
                    const char* wk = sm + OFF_W
                                   + (u32)(((p * 4 + kb) * 8 + 2 * nq) * 512)
                                   + (u32)lane * 16u;
                    uint4 B0 = *(const uint4*)(wk);
                    uint4 B1 = *(const uint4*)(wk + 512);
                    uint4 A0 = *(const uint4*)(ab + kb * 512);
                    mma16(dd[0][0][0], dd[0][0][1], dd[0][0][2], dd[0][0][3],
                          A0.x, A0.y, A0.z, A0.w, B0.x, B0.y);
                    mma16(dd[0][1][0], dd[0][1][1], dd[0][1][2], dd[0][1][3],
                          A0.x, A0.y, A0.z, A0.w, B0.z, B0.w);
                    mma16(dd[0][2][0], dd[0][2][1], dd[0][2][2], dd[0][2][3],
                          A0.x, A0.y, A0.z, A0.w, B1.x, B1.y);
                    mma16(dd[0][3][0], dd[0][3][1], dd[0][3][2], dd[0][3][3],
                          A0.x, A0.y, A0.z, A0.w, B1.z, B1.w);
                    uint4 A1 = *(const uint4*)(ab + 2048 + kb * 512);
                    mma16(dd[1][0][0], dd[1][0][1], dd[1][0][2], dd[1][0][3],
                          A1.x, A1.y, A1.z, A1.w, B0.x, B0.y);
                    mma16(dd[1][1][0], dd[1][1][1], dd[1][1][2], dd[1][1][3],
                          A1.x, A1.y, A1.z, A1.w, B0.z, B0.w);
                    mma16(dd[1][2][0], dd[1][2][1], dd[1][2][2], dd[1][2][3],
                          A1.x, A1.y, A1.z, A1.w, B1.x, B1.y);
                    mma16(dd[1][3][0], dd[1][3][1], dd[1][3][2], dd[1][3][3],
                          A1.x, A1.y, A1.z, A1.w, B1.z, B1.w);
                }
                if (p == 3) {   // stats kb16 (K index 16)
                    const char* sb = sm + OFF_XS + (u32)(2 * mp) * 512u
                                   + (u32)swz_l * 4u;
                    const char* wk = sm + OFF_W
                                   + (u32)((16 * 8 + 2 * nq) * 512) + (u32)lane * 16u;
                    uint4 B0 = *(const uint4*)(wk);
                    uint4 B1 = *(const uint4*)(wk + 512);
                    uint4 A0 = *(const uint4*)(sb);
                    mma16(dd[0][0][0], dd[0][0][1], dd[0][0][2], dd[0][0][3],
                          A0.x, A0.y, A0.z, A0.w, B0.x, B0.y);
                    mma16(dd[0][1][0], dd[0][1][1], dd[0][1][2], dd[0][1][3],
                          A0.x, A0.y, A0.z, A0.w, B0.z, B0.w);
                    mma16(dd[0][2][0], dd[0][2][1], dd[0][2][2], dd[0][2][3],
                          A0.x, A0.y, A0.z, A0.w, B1.x, B1.y);
                    mma16(dd[0][3][0], dd[0][3][1], dd[0][3][2], dd[0][3][3],
                          A0.x, A0.y, A0.z, A0.w, B1.z, B1.w);
                    uint4 A1 = *(const uint4*)(sb + 512);
                    mma16(dd[1][0][0], dd[1][0][1], dd[1][0][2], dd[1][0][3],
                          A1.x, A1.y, A1.z, A1.w, B0.x, B0.y);
                    mma16(dd[1][1][0], dd[1][1][1], dd[1][1][2], dd[1][1][3],
                          A1.x, A1.y, A1.z, A1.w, B0.z, B0.w);
                    mma16(dd[1][2][0], dd[1][2][1], dd[1][2][2], dd[1][2][3],
                          A1.x, A1.y, A1.z, A1.w, B1.x, B1.y);
                    mma16(dd[1][3][0], dd[1][3][1], dd[1][3][2], dd[1][3][3],
                          A1.x, A1.y, A1.z, A1.w, B1.z, B1.w);
                }
            }
        } // p loop

        if (tt + 148 < 512) {
            const float* src = br0 + (size_t)((tt + 148) * 8 + lmt) * 1024
                             + lr * 64 + lq * 16;
#pragma unroll
            for (int j = 0; j < 4; j++) v[j] = *(const float4*)(src + j * 4);
        }

        // ---- epilogue (identical structure to R14) ----
        const float* Hsf = (const float*)(sm + OFF_HS);
        const float* W2s = (const float*)(sm + OFF_W2);
#pragma unroll
        for (int mt = 0; mt < 2; mt++) {
            float LA[4] = {0.f, 0.f, 0.f, 0.f}, LB[4] = {0.f, 0.f, 0.f, 0.f};
            const float* hrow = Hsf + (2 * mp + mt) * 128;
#pragma unroll
            for (int nbl = 0; nbl < 4; nbl++) {
                int n0 = (nq * 4 + nbl) * 8 + tig * 2;
                float4 wa = *(const float4*)&W2s[n0 * 4];
                float4 wb = *(const float4*)&W2s[n0 * 4 + 4];
                float2 hc = *(const float2*)&hrow[n0];
                float h00 = gelu_f(dd[mt][nbl][0] + hc.x);
                float h01 = gelu_f(dd[mt][nbl][1] + hc.y);
                float h10 = gelu_f(dd[mt][nbl][2] + hc.x);
                float h11 = gelu_f(dd[mt][nbl][3] + hc.y);
                LA[0] += h00 * wa.x + h01 * wb.x; LA[1] += h00 * wa.y + h01 * wb.y;
                LA[2] += h00 * wa.z + h01 * wb.z; LA[3] += h00 * wa.w + h01 * wb.w;
                LB[0] += h10 * wa.x + h11 * wb.x; LB[1] += h10 * wa.y + h11 * wb.y;
                LB[2] += h10 * wa.z + h11 * wb.z; LB[3] += h10 * wa.w + h11 * wb.w;
            }
#pragma unroll
            for (int off = 1; off <= 2; off <<= 1) {
#pragma unroll
                for (int q = 0; q < 4; q++) {
                    LA[q] += __shfl_xor_sync(0xffffffffu, LA[q], off);
                    LB[q] += __shfl_xor_sync(0xffffffffu, LB[q], off);
                }
            }
            if (tig == 0) {
                float4* Ls = (float4*)(sm + OFF_LS);
                int r = (2 * mp + mt) * 16 + gid;
                Ls[nq * 128 + r]     = make_float4(LA[0], LA[1], LA[2], LA[3]);
                Ls[nq * 128 + r + 8] = make_float4(LB[0], LB[1], LB[2], LB[3]);
            }
        }
        __syncthreads();
        if (tid < 128) {
            const float4* Ls = (const float4*)(sm + OFF_LS);
            float4 p0 = Ls[tid], p1 = Ls[128 + tid];
            float4 p2 = Ls[256 + tid], p3 = Ls[384 + tid];
            float l0 = p0.x + p1.x + p2.x + p3.x + b2v.x;
            float l1 = p0.y + p1.y + p2.y + p3.y + b2v.y;
            float l2 = p0.z + p1.z + p2.z + p3.z + b2v.z;
            float l3 = p0.w + p1.w + p2.w + p3.w + b2v.w;
            float s0 = l0 * it_h, s1 = l1 * it_h, s2 = l2 * it_h, s3 = l3 * it_h;
            float m = fmaxf(fmaxf(s0, s1), fmaxf(s2, s3));
            float e0 = expf(s0 - m), e1 = expf(s1 - m);
            float e2 = expf(s2 - m), e3 = expf(s3 - m);
            float inv = 1.f / (e0 + e1 + e2 + e3);
            float w0 = fmaxf(e0 * inv, fl_h.x);
            float w1 = fmaxf(e1 * inv, fl_h.y);
            float w2_ = fmaxf(e2 * inv, fl_h.z);
            float w3 = fmaxf(e3 * inv, fl_h.w);
            float inv2 = 1.f / (w0 + w1 + w2_ + w3);
            int bl = tid >> 4, head = tid & 15;
            *(float4*)(out + (size_t)(base + bl) * 64 + head * 4) =
                make_float4(w0 * inv2, w1 * inv2, w2_ * inv2, w3 * inv2);
        }
        __syncthreads();
    }
}

// ---------------------------------------------------------------------------
extern "C" void kernel_launch(void* const* d_in, const int* in_sizes, int n_in,
                              void* d_out, int out_size) {
    (void)in_sizes; (void)n_in; (void)out_size;
    const float* hidden = (const float*)d_in[0];
    const float* b0     = (const float*)d_in[1];
    const float* b1br   = (const float*)d_in[2];
    const float* b2br   = (const float*)d_in[3];
    const float* b3br   = (const float*)d_in[4];
    const float* W1     = (const float*)d_in[5];
    const float* b1     = (const float*)d_in[6];
    const float* W2     = (const float*)d_in[7];
    const float* b2     = (const float*)d_in[8];
    const float* eps    = (const float*)d_in[9];
    const float* temp   = (const float*)d_in[10];
    float* out = (float*)d_out;

    cudaFuncSetAttribute(prep_mma, cudaFuncAttributeMaxDynamicSharedMemorySize,
                         (int)PREP_SMEM);
    cudaFuncSetAttribute(gate_mma, cudaFuncAttributeMaxDynamicSharedMemorySize,
                         (int)SM_TOT);

    prep_mma<<<148, 512, PREP_SMEM>>>(hidden, W1, b1);
    gate_mma<<<148, 512, SM_TOT>>>(b0, b1br, b2br, b3br, W2, b2, eps, temp, out);
}

// round 17
// speedup vs baseline: 1.4134x; 1.1690x over previous
#include <cuda_runtime.h>
#include <math.h>
#include <stdint.h>

#define NBL  4096
#define HIDD 1024
#define OUTC 128
typedef unsigned long long ull;
typedef uint32_t u32;

// ---------------- device scratch (allocation-free rule) ----------------
__device__ __align__(16) float g_Hc[NBL * OUTC];   // hidden @ W1[0:1024] + b1
__device__ __align__(16) float g_Wt[34816];        // gate W fragments (f16 pairs)

// ---------------- helpers ----------------
__device__ __forceinline__ float gelu_f(float x) {
    return 0.5f * x * (1.0f + erff(x * 0.70710678118654752440f));
}
__device__ __forceinline__ u32 pkf16(float lo, float hi) {
    u32 d;
    asm("cvt.rn.f16x2.f32 %0, %1, %2;" : "=r"(d) : "f"(hi), "f"(lo));
    return d;
}
__device__ __forceinline__ void mma16(float& d0, float& d1, float& d2, float& d3,
                                      u32 a0, u32 a1, u32 a2, u32 a3,
                                      u32 b0, u32 b1) {
    asm volatile("mma.sync.aligned.m16n8k16.row.col.f32.f16.f16.f32 "
                 "{%0,%1,%2,%3}, {%4,%5,%6,%7}, {%8,%9}, {%0,%1,%2,%3};"
                 : "+f"(d0), "+f"(d1), "+f"(d2), "+f"(d3)
                 : "r"(a0), "r"(a1), "r"(a2), "r"(a3), "r"(b0), "r"(b1));
}
__device__ __forceinline__ void barg(int id) {
    asm volatile("bar.sync %0, 256;" :: "r"(id) : "memory");
}

// ---------------------------------------------------------------------------
// prep_mma (512 threads, grid 148):
//  blocks 0..127   : g_Hc = hidden @ W1[0:1024] + b1 (f16 k16 mma, split-K)
//  blocks 128..147 : gate-W build units u (stride 20, u < 23)  [R16 verbatim]
// ---------------------------------------------------------------------------
#define PREP_SMEM (10240 * 4)   // Af 2x1024 + Bf 2x4096 words = 40KB

__global__ __launch_bounds__(512) void prep_mma(const float* __restrict__ A,
                                                const float* __restrict__ W1,
                                                const float* __restrict__ b1) {
    const int tid = threadIdx.x;

    if (blockIdx.x >= 128) {
        u32* dst = (u32*)g_Wt;
#pragma unroll 1
        for (int u = blockIdx.x - 128; u < 23; u += 20) {
            if (u < 16) {
                int K = u;
#pragma unroll
                for (int i = 0; i < 2; i++) {
                    int gi = tid + i * 512;       // 0..1023
                    int p4 = gi >> 7, n = gi & 127;
                    float f0 = W1[(size_t)(1792 + K * 16 + p4 * 2) * 128 + n];
                    float f1 = W1[(size_t)(1792 + K * 16 + p4 * 2 + 1) * 128 + n];
                    dst[(u32)((K * 8 + (n >> 4)) * 128
                        + ((n & 7) * 4 + (p4 & 3)) * 4 + ((n >> 3) & 1) * 2 + (p4 >> 2))]
                        = pkf16(f0, f1);
                }
            } else if (u < 22) {
                int v = u - 16;                   // pair (s=2v, 2v+1)
                int n = tid >> 2, q = tid & 3;
                const float* p0 = W1 + (size_t)(1024 + (2 * v) * 64 + q * 16) * 128 + n;
                const float* p1 = W1 + (size_t)(1024 + (2 * v + 1) * 64 + q * 16) * 128 + n;
                float a0 = 0.f, a1 = 0.f;
#pragma unroll
                for (int r = 0; r < 16; r++) {
                    a0 += p0[(size_t)r * 128];
                    a1 += p1[(size_t)r * 128];
                }
                a0 += __shfl_xor_sync(0xffffffffu, a0, 1);
                a0 += __shfl_xor_sync(0xffffffffu, a0, 2);
                a1 += __shfl_xor_sync(0xffffffffu, a1, 1);
                a1 += __shfl_xor_sync(0xffffffffu, a1, 2);
                if (q == 0) {
                    dst[(u32)((16 * 8 + (n >> 4)) * 128
                        + ((n & 7) * 4 + (v & 3)) * 4 + ((n >> 3) & 1) * 2 + (v >> 2))]
                        = pkf16(a0, a1);
                }
            } else {
                if (tid < 256) {
                    int p4 = 6 + (tid >> 7), n = tid & 127;
                    dst[(u32)((16 * 8 + (n >> 4)) * 128
                        + ((n & 7) * 4 + (p4 & 3)) * 4 + ((n >> 3) & 1) * 2 + (p4 >> 2))]
                        = 0u;
                }
            }
        }
        return;
    }

    // ---- GEMM: f16 k16, split-K dual pipelines ----
    extern __shared__ u32 smw[];
    u32* Af = smw;          // [2][1024] words (f16 pairs, [mtile][kb16][128])
    u32* Bf = smw + 2048;   // [2][4096] words (paired-nb, [kb16][np][128])

    const int kg   = tid >> 8;        // group 0/1
    const int gtid = tid & 255;
    const int m0 = blockIdx.x * 32;
    const int lane = gtid & 31, warp = gtid >> 5;
    const int mg = warp & 1, ng = warp >> 1;        // mg: mtile, ng: 4-nb group

    // A-writer: thread -> row ar (0..31), sub: kb16 + half
    const int ar = gtid >> 3;
    const int amt = ar >> 4;           // mtile 0/1
    const int alr = ar & 15;
    const int arlow = alr & 7, arhi = (alr >= 8) ? 1 : 0;
    const int asub = gtid & 7;
    const int akb16 = asub >> 1, ahalf = asub & 1;
    const u32 aswz = (u32)(arlow << 2);
    const float* Ag = A + (size_t)(m0 + ar) * HIDD + akb16 * 16 + ahalf * 8;

    // B-writer: thread -> k-pair kp (0..31), n block of 16
    const int kp = gtid >> 3;
    const int bkb = kp >> 3, bp4 = kp & 7;
    const int bn0 = (gtid & 7) * 16;
    const float* Bg = W1 + (size_t)(2 * kp) * OUTC + bn0;

    // reader swizzle
    const int swz_l = (lane * 4) ^ ((lane >> 2) << 2);

    float d[4][4];
#pragma unroll
    for (int i = 0; i < 4; i++)
#pragma unroll
        for (int j = 0; j < 4; j++) d[i][j] = 0.f;

    float av[8];
    float bv[32];

#define LDGA(CK) do {                                                  \
    float4 t0 = *(const float4*)(Ag + (CK) * 64);                      \
    float4 t1 = *(const float4*)(Ag + (CK) * 64 + 4);                  \
    av[0]=t0.x; av[1]=t0.y; av[2]=t0.z; av[3]=t0.w;                    \
    av[4]=t1.x; av[5]=t1.y; av[6]=t1.z; av[7]=t1.w;                    \
} while (0)

#define LDGB(CK) do {                                                  \
    const float* bg_ = Bg + (size_t)(CK) * 64 * OUTC;                  \
    _Pragma("unroll")                                                  \
    for (int g_ = 0; g_ < 4; g_++) {                                   \
        float4 t_ = *(const float4*)(bg_ + g_ * 4);                    \
        bv[g_*4+0]=t_.x; bv[g_*4+1]=t_.y; bv[g_*4+2]=t_.z; bv[g_*4+3]=t_.w;  \
    }                                                                  \
    _Pragma("unroll")                                                  \
    for (int g_ = 0; g_ < 4; g_++) {                                   \
        float4 t_ = *(const float4*)(bg_ + OUTC + g_ * 4);             \
        bv[16+g_*4+0]=t_.x; bv[16+g_*4+1]=t_.y; bv[16+g_*4+2]=t_.z; bv[16+g_*4+3]=t_.w; \
    }                                                                  \
} while (0)

#define STORE(BUF) do {                                                \
    _Pragma("unroll")                                                  \
    for (int j_ = 0; j_ < 4; j_++) {                                   \
        u32 off_ = (u32)(arlow * 16 + j_ * 4 + arhi + (ahalf ? 2 : 0)) ^ aswz; \
        Af[(BUF) * 1024 + (amt * 4 + akb16) * 128 + off_] =            \
            pkf16(av[2 * j_], av[2 * j_ + 1]);                         \
    }                                                                  \
    _Pragma("unroll")                                                  \
    for (int nn_ = 0; nn_ < 16; nn_++) {                               \
        int n_ = bn0 + nn_;                                            \
        u32 w_ = (u32)((bkb * 8 + (n_ >> 4)) * 128                     \
               + ((n_ & 7) * 4 + (bp4 & 3)) * 4 + ((n_ >> 3) & 1) * 2 + (bp4 >> 2)); \
        Bf[(BUF) * 4096 + w_] = pkf16(bv[nn_], bv[16 + nn_]);          \
    }                                                                  \
} while (0)

#define MMACHUNK(BUF) do {                                             \
    _Pragma("unroll")                                                  \
    for (int kb_ = 0; kb_ < 4; kb_++) {                                \
        uint4 Av_ = *(const uint4*)&Af[(BUF) * 1024 + (mg * 4 + kb_) * 128 + swz_l]; \
        const u32* wk_ = &Bf[(BUF) * 4096 + (kb_ * 8 + 2 * ng) * 128 + lane * 4]; \
        uint4 B0_ = *(const uint4*)(wk_);                              \
        uint4 B1_ = *(const uint4*)(wk_ + 128);                        \
        mma16(d[0][0], d[0][1], d[0][2], d[0][3],                      \
              Av_.x, Av_.y, Av_.z, Av_.w, B0_.x, B0_.y);               \
        mma16(d[1][0], d[1][1], d[1][2], d[1][3],                      \
              Av_.x, Av_.y, Av_.z, Av_.w, B0_.z, B0_.w);               \
        mma16(d[2][0], d[2][1], d[2][2], d[2][3],                      \
              Av_.x, Av_.y, Av_.z, Av_.w, B1_.x, B1_.y);               \
        mma16(d[3][0], d[3][1], d[3][2], d[3][3],                      \
              Av_.x, Av_.y, Av_.z, Av_.w, B1_.z, B1_.w);               \
    }                                                                  \
} while (0)

    // group kg handles chunks kg, kg+2, ..., 14+kg
    LDGA(kg); LDGB(kg);
    STORE(kg);
    barg(1 + kg);

#pragma unroll 1
    for (int c = kg; c < 16; c += 2) {
        if (c + 2 < 16) { LDGA(c + 2); LDGB(c + 2); }
        MMACHUNK(kg);
        if (c + 2 < 16) {
            barg(1 + kg);
            STORE(kg);
            barg(1 + kg);
        }
    }

    // ---- cross-group reduction ----
    __syncthreads();
    if (kg == 1) {
        float4* ps = (float4*)smw;       // 16KB, fits 40KB smem
#pragma unroll
        for (int q = 0; q < 4; q++)
            ps[gtid * 4 + q] = make_float4(d[q][0], d[q][1], d[q][2], d[q][3]);
    }
    __syncthreads();
    if (kg == 0) {
        const float4* ps = (const float4*)smw;
#pragma unroll
        for (int q = 0; q < 4; q++) {
            float4 o = ps[gtid * 4 + q];
            d[q][0] += o.x; d[q][1] += o.y; d[q][2] += o.z; d[q][3] += o.w;
        }
        const int row0 = m0 + mg * 16 + (lane >> 2);
        const int col0 = ng * 32 + (lane & 3) * 2;
#pragma unroll
        for (int q = 0; q < 4; q++) {
            int col = col0 + q * 8;
            float2 bb = *(const float2*)(b1 + col);
            *(float2*)&g_Hc[(size_t)row0 * OUTC + col] =
                make_float2(d[q][0] + bb.x, d[q][1] + bb.y);
            *(float2*)&g_Hc[(size_t)(row0 + 8) * OUTC + col] =
                make_float2(d[q][2] + bb.x, d[q][3] + bb.y);
        }
    }
}

// ---------------------------------------------------------------------------
// gate_mma: persistent f16 m16n8k16 gate kernel (R16 verbatim).
// ---------------------------------------------------------------------------
#define OFF_W    0u
#define OFF_X    69632u
#define OFF_XS   102400u
#define OFF_XSTG 106496u
#define OFF_HS   112640u
#define OFF_LS   116736u
#define OFF_W2   124928u
#define SM_TOT   126976u

__global__ __launch_bounds__(512, 1) void gate_mma(
    const float* __restrict__ br0, const float* __restrict__ br1,
    const float* __restrict__ br2, const float* __restrict__ br3,
    const float* __restrict__ W2,  const float* __restrict__ b2,
    const float* __restrict__ eps, const float* __restrict__ temp,
    float* __restrict__ out)
{
    extern __shared__ char sm[];
    const int tid  = threadIdx.x;
    const int lane = tid & 31, warp = tid >> 5;
    const int mp = warp >> 2, nq = warp & 3;

    {
        const float4* s = (const float4*)g_Wt;
        float4* d = (float4*)(sm + OFF_W);
        for (int i = tid; i < 4352; i += 512) d[i] = s[i];
    }
    {
        float4* d = (float4*)(sm + OFF_XS);
        if (tid < 256) d[tid] = make_float4(0.f, 0.f, 0.f, 0.f);
    }
    {
        float* d = (float*)(sm + OFF_W2);
        d[tid] = W2[tid & 511];
    }
    const float4 b2v = *(const float4*)b2;
    float it_h = 1.f;
    float4 fl_h = make_float4(0.f, 0.f, 0.f, 0.f);
    if (tid < 128) {
        int head = tid & 15;
        it_h = 1.f / fminf(fmaxf(temp[head], 0.2f), 10.0f);
        float4 ef = *(const float4*)(eps + head * 4);
        fl_h.x = fminf(fmaxf(ef.x, 1e-7f), 0.1f);
        fl_h.y = fminf(fmaxf(ef.y, 1e-7f), 0.1f);
        fl_h.z = fminf(fmaxf(ef.z, 1e-7f), 0.1f);
        fl_h.w = fminf(fmaxf(ef.w, 1e-7f), 0.1f);
    }
    __syncthreads();

    const int lm = tid >> 2, lq = tid & 3;
    const int lmt = lm >> 4;
    const int lr  = lm & 15;
    const int rlow = lr & 7, rhi = (lr >= 8) ? 1 : 0;
    const int swzr = rlow << 2;
    const int swz_l = (lane * 4) ^ ((lane >> 2) << 2);
    const int tig = lane & 3, gid = lane >> 2;

    float4 v[4];
    int tt = blockIdx.x;
    {
        const float* src = br0 + (size_t)(tt * 8 + lmt) * 1024 + lr * 64 + lq * 16;
#pragma unroll
        for (int j = 0; j < 4; j++) v[j] = *(const float4*)(src + j * 4);
    }

    for (; tt < 512; tt += 148) {
        const int base = tt * 8;

        if (tid < 256) {
            const float4* s = (const float4*)(g_Hc + (size_t)base * 128);
            ((float4*)(sm + OFF_HS))[tid] = s[tid];
        }

        float dd[2][4][4];
#pragma unroll
        for (int mt = 0; mt < 2; mt++)
#pragma unroll
            for (int nb = 0; nb < 4; nb++)
#pragma unroll
                for (int c = 0; c < 4; c++) dd[mt][nb][c] = 0.f;

#pragma unroll 1
        for (int p = 0; p < 4; p++) {
            float s = 0.f, q2 = 0.f, mx = -INFINITY;
#pragma unroll
            for (int j = 0; j < 4; j++) {
                s  += (v[j].x + v[j].y) + (v[j].z + v[j].w);
                q2 += v[j].x * v[j].x + v[j].y * v[j].y
                    + v[j].z * v[j].z + v[j].w * v[j].w;
                mx = fmaxf(mx, fmaxf(fmaxf(v[j].x, v[j].y), fmaxf(v[j].z, v[j].w)));
            }
            s  += __shfl_xor_sync(0xffffffffu, s, 1);
            q2 += __shfl_xor_sync(0xffffffffu, q2, 1);
            mx  = fmaxf(mx, __shfl_xor_sync(0xffffffffu, mx, 1));
            s  += __shfl_xor_sync(0xffffffffu, s, 2);
            q2 += __shfl_xor_sync(0xffffffffu, q2, 2);
            mx  = fmaxf(mx, __shfl_xor_sync(0xffffffffu, mx, 2));

            {
                u32* xb = (u32*)(sm + OFF_X) + (p & 1) * 4096 + lmt * 512 + lq * 128;
                const float* vf = (const float*)v;
#pragma unroll
                for (int j = 0; j < 8; j++) {
                    int off = (rlow * 16 + (j & 3) * 4 + rhi + ((j >= 4) ? 2 : 0)) ^ swzr;
                    xb[off] = pkf16(vf[2 * j], vf[2 * j + 1]);
                }
                if (lq == 0) {
                    float st0 = s * (1.f / 64.f);
                    float st1 = sqrtf(fmaxf(q2 * (1.f / 64.f), 1e-8f));
                    float st2 = mx;
                    float* xstg = (float*)(sm + OFF_XSTG);
                    xstg[(lmt * 16 + lr) * 12 + p * 3 + 0] = st0;
                    xstg[(lmt * 16 + lr) * 12 + p * 3 + 1] = st1;
                    xstg[(lmt * 16 + lr) * 12 + p * 3 + 2] = st2;
                }
            }
            __syncthreads();

            if (p < 3) {
                const float* bp = (p == 0) ? br1 : (p == 1) ? br2 : br3;
                const float* src = bp + (size_t)(base + lmt) * 1024 + lr * 64 + lq * 16;
#pragma unroll
                for (int j = 0; j < 4; j++) v[j] = *(const float4*)(src + j * 4);
            }

            if (p == 3) {
                const float* xstg = (const float*)(sm + OFF_XSTG);
                u32* xsf = (u32*)(sm + OFF_XS);
#pragma unroll 2
                for (int i = tid; i < 768; i += 512) {
                    int mt = i / 96, rem = i % 96;
                    int r = rem / 6, p4 = rem % 6;
                    float lo = xstg[(mt * 16 + r) * 12 + 2 * p4];
                    float hi = xstg[(mt * 16 + r) * 12 + 2 * p4 + 1];
                    int off = ((r & 7) * 16 + (p4 & 3) * 4 + ((r >= 8) ? 1 : 0)
                             + ((p4 >= 4) ? 2 : 0)) ^ ((r & 7) << 2);
                    xsf[mt * 128 + off] = pkf16(lo, hi);
                }
                __syncthreads();
            }

            {
                const char* xbase = sm + OFF_X + (p & 1) * 16384u;
                const char* ab = xbase + (u32)(2 * mp) * 2048u + (u32)swz_l * 4u;
#pragma unroll
                for (int kb = 0; kb < 4; kb++) {
                    const char* wk = sm + OFF_W
                                   + (u32)(((p * 4 + kb) * 8 + 2 * nq) * 512)
                                   + (u32)lane * 16u;
                    uint4 B0 = *(const uint4*)(wk);
                    uint4 B1 = *(const uint4*)(wk + 512);
                    uint4 A0 = *(const uint4*)(ab + kb * 512);
                    mma16(dd[0][0][0], dd[0][0][1], dd[0][0][2], dd[0][0][3],
                          A0.x, A0.y, A0.z, A0.w, B0.x, B0.y);
                    mma16(dd[0][1][0], dd[0][1][1], dd[0][1][2], dd[0][1][3],
                          A0.x, A0.y, A0.z, A0.w, B0.z, B0.w);
                    mma16(dd[0][2][0], dd[0][2][1], dd[0][2][2], dd[0][2][3],
                          A0.x, A0.y, A0.z, A0.w, B1.x, B1.y);
                    mma16(dd[0][3][0], dd[0][3][1], dd[0][3][2], dd[0][3][3],
                          A0.x, A0.y, A0.z, A0.w, B1.z, B1.w);
                    uint4 A1 = *(const uint4*)(ab + 2048 + kb * 512);
                    mma16(dd[1][0][0], dd[1][0][1], dd[1][0][2], dd[1][0][3],
                          A1.x, A1.y, A1.z, A1.w, B0.x, B0.y);
                    mma16(dd[1][1][0], dd[1][1][1], dd[1][1][2], dd[1][1][3],
                          A1.x, A1.y, A1.z, A1.w, B0.z, B0.w);
                    mma16(dd[1][2][0], dd[1][2][1], dd[1][2][2], dd[1][2][3],
                          A1.x, A1.y, A1.z, A1.w, B1.x, B1.y);
                    mma16(dd[1][3][0], dd[1][3][1], dd[1][3][2], dd[1][3][3],
                          A1.x, A1.y, A1.z, A1.w, B1.z, B1.w);
                }
                if (p == 3) {
                    const char* sb = sm + OFF_XS + (u32)(2 * mp) * 512u
                                   + (u32)swz_l * 4u;
                    const char* wk = sm + OFF_W
                                   + (u32)((16 * 8 + 2 * nq) * 512) + (u32)lane * 16u;
                    uint4 B0 = *(const uint4*)(wk);
                    uint4 B1 = *(const uint4*)(wk + 512);
                    uint4 A0 = *(const uint4*)(sb);
                    mma16(dd[0][0][0], dd[0][0][1], dd[0][0][2], dd[0][0][3],
                          A0.x, A0.y, A0.z, A0.w, B0.x, B0.y);
                    mma16(dd[0][1][0], dd[0][1][1], dd[0][1][2], dd[0][1][3],
                          A0.x, A0.y, A0.z, A0.w, B0.z, B0.w);
                    mma16(dd[0][2][0], dd[0][2][1], dd[0][2][2], dd[0][2][3],
                          A0.x, A0.y, A0.z, A0.w, B1.x, B1.y);
                    mma16(dd[0][3][0], dd[0][3][1], dd[0][3][2], dd[0][3][3],
                          A0.x, A0.y, A0.z, A0.w, B1.z, B1.w);
                    uint4 A1 = *(const uint4*)(sb + 512);
                    mma16(dd[1][0][0], dd[1][0][1], dd[1][0][2], dd[1][0][3],
                          A1.x, A1.y, A1.z, A1.w, B0.x, B0.y);
                    mma16(dd[1][1][0], dd[1][1][1], dd[1][1][2], dd[1][1][3],
                          A1.x, A1.y, A1.z, A1.w, B0.z, B0.w);
                    mma16(dd[1][2][0], dd[1][2][1], dd[1][2][2], dd[1][2][3],
                          A1.x, A1.y, A1.z, A1.w, B1.x, B1.y);
                    mma16(dd[1][3][0], dd[1][3][1], dd[1][3][2], dd[1][3][3],
                          A1.x, A1.y, A1.z, A1.w, B1.z, B1.w);
                }
            }
        } // p loop

        if (tt + 148 < 512) {
            const float* src = br0 + (size_t)((tt + 148) * 8 + lmt) * 1024
                             + lr * 64 + lq * 16;
#pragma unroll
            for (int j = 0; j < 4; j++) v[j] = *(const float4*)(src + j * 4);
        }

        const float* Hsf = (const float*)(sm + OFF_HS);
        const float* W2s = (const float*)(sm + OFF_W2);
#pragma unroll
        for (int mt = 0; mt < 2; mt++) {
            float LA[4] = {0.f, 0.f, 0.f, 0.f}, LB[4] = {0.f, 0.f, 0.f, 0.f};
            const float* hrow = Hsf + (2 * mp + mt) * 128;
#pragma unroll
            for (int nbl = 0; nbl < 4; nbl++) {
                int n0 = (nq * 4 + nbl) * 8 + tig * 2;
                float4 wa = *(const float4*)&W2s[n0 * 4];
                float4 wb = *(const float4*)&W2s[n0 * 4 + 4];
                float2 hc = *(const float2*)&hrow[n0];
                float h00 = gelu_f(dd[mt][nbl][0] + hc.x);
                float h01 = gelu_f(dd[mt][nbl][1] + hc.y);
                float h10 = gelu_f(dd[mt][nbl][2] + hc.x);
                float h11 = gelu_f(dd[mt][nbl][3] + hc.y);
                LA[0] += h00 * wa.x + h01 * wb.x; LA[1] += h00 * wa.y + h01 * wb.y;
                LA[2] += h00 * wa.z + h01 * wb.z; LA[3] += h00 * wa.w + h01 * wb.w;
                LB[0] += h10 * wa.x + h11 * wb.x; LB[1] += h10 * wa.y + h11 * wb.y;
                LB[2] += h10 * wa.z + h11 * wb.z; LB[3] += h10 * wa.w + h11 * wb.w;
            }
#pragma unroll
            for (int off = 1; off <= 2; off <<= 1) {
#pragma unroll
                for (int q = 0; q < 4; q++) {
                    LA[q] += __shfl_xor_sync(0xffffffffu, LA[q], off);
                    LB[q] += __shfl_xor_sync(0xffffffffu, LB[q], off);
                }
            }
            if (tig == 0) {
                float4* Ls = (float4*)(sm + OFF_LS);
                int r = (2 * mp + mt) * 16 + gid;
                Ls[nq * 128 + r]     = make_float4(LA[0], LA[1], LA[2], LA[3]);
                Ls[nq * 128 + r + 8] = make_float4(LB[0], LB[1], LB[2], LB[3]);
            }
        }
        __syncthreads();
        if (tid < 128) {
            const float4* Ls = (const float4*)(sm + OFF_LS);
            float4 p0 = Ls[tid], p1 = Ls[128 + tid];
            float4 p2 = Ls[256 + tid], p3 = Ls[384 + tid];
            float l0 = p0.x + p1.x + p2.x + p3.x + b2v.x;
            float l1 = p0.y + p1.y + p2.y + p3.y + b2v.y;
            float l2 = p0.z + p1.z + p2.z + p3.z + b2v.z;
            float l3 = p0.w + p1.w + p2.w + p3.w + b2v.w;
            float s0 = l0 * it_h, s1 = l1 * it_h, s2 = l2 * it_h, s3 = l3 * it_h;
            float m = fmaxf(fmaxf(s0, s1), fmaxf(s2, s3));
            float e0 = expf(s0 - m), e1 = expf(s1 - m);
            float e2 = expf(s2 - m), e3 = expf(s3 - m);
            float inv = 1.f / (e0 + e1 + e2 + e3);
            float w0 = fmaxf(e0 * inv, fl_h.x);
            float w1 = fmaxf(e1 * inv, fl_h.y);
            float w2_ = fmaxf(e2 * inv, fl_h.z);
            float w3 = fmaxf(e3 * inv, fl_h.w);
            float inv2 = 1.f / (w0 + w1 + w2_ + w3);
            int bl = tid >> 4, head = tid & 15;
            *(float4*)(out + (size_t)(base + bl) * 64 + head * 4) =
                make_float4(w0 * inv2, w1 * inv2, w2_ * inv2, w3 * inv2);
        }
        __syncthreads();
    }
}

// ---------------------------------------------------------------------------
extern "C" void kernel_launch(void* const* d_in, const int* in_sizes, int n_in,
                              void* d_out, int out_size) {
    (void)in_sizes; (void)n_in; (void)out_size;
    const float* hidden = (const float*)d_in[0];
    const float* b0     = (const float*)d_in[1];
    const float* b1br   = (const float*)d_in[2];
    const float* b2br   = (const float*)d_in[3];
    const float* b3br   = (const float*)d_in[4];
    const float* W1     = (const float*)d_in[5];
    const float* b1     = (const float*)d_in[6];
    const float* W2     = (const float*)d_in[7];
    const float* b2     = (const float*)d_in[8];
    const float* eps    = (const float*)d_in[9];
    const float* temp   = (const float*)d_in[10];
    float* out = (float*)d_out;

    cudaFuncSetAttribute(prep_mma, cudaFuncAttributeMaxDynamicSharedMemorySize,
                         (int)PREP_SMEM);
    cudaFuncSetAttribute(gate_mma, cudaFuncAttributeMaxDynamicSharedMemorySize,
                         (int)SM_TOT);

    prep_mma<<<148, 512, PREP_SMEM>>>(hidden, W1, b1);
    gate_mma<<<148, 512, SM_TOT>>>(b0, b1br, b2br, b3br, W2, b2, eps, temp, out);
}